// round 9
// baseline (speedup 1.0000x reference)
#include <cuda_runtime.h>

// UniSAGE is fully linear => pull the final averaging functionals backwards.
// R9: R8 core (NNZ chain at LSU random-op floor, 9 ops/incidence, op-minimal).
// Optimize the reduce: 2 vertices/thread -> x0 read as 7 aligned float4s
// (0.5M LSU ops instead of 1.4M scalar), p2 as float2, pv4 pair. __ldcg on
// L2-resident gathers.

#define NV   100000
#define NE   200000
#define NNZt 800000
#define DIN  14
#define HID  128
#define WP   (1.0f / (float)NV)
#define WR   (1.0f / (float)NE)

// NNZ pass geometry: 8 elems/thread (proven shape).
#define NNZ_BLK   256
#define NNZ_GRID  ((NNZt / 8 + NNZ_BLK - 1) / NNZ_BLK)   // 391
#define NNZ_THREADS (NNZt / 8)                            // 100000

// reduce geometry: 2 vertices/thread
#define RED_BLK   256
#define RED_GRID  ((NV / 2 + RED_BLK - 1) / RED_BLK)      // 196

// -------- device scratch (allocation-free), zeroed by one memset ----
struct Scratch {
    float4 pv4[NV];    // {p_raw, r2_raw, deg, pad}
    float  p2 [NV];    // p2_raw
    float2 ze [NE];    // {zp, edeg}
    float  zp2[NE];
    float  acc[32];    // [0..13]=p2^T X, [14..27]=r2^T X, 28=Σp, 29=Σp2, 30=Σr2
    unsigned int tick;
};
__device__ Scratch g_s;

__device__ __forceinline__ void red2(float2* a, float x, float y) {
    asm volatile("red.global.add.v2.f32 [%0], {%1,%2};" :: "l"(a), "f"(x), "f"(y) : "memory");
}
__device__ __forceinline__ void red1(float* a, float x) {
    asm volatile("red.global.add.f32 [%0], %1;" :: "l"(a), "f"(x) : "memory");
}

// ---- phase 1: vertex degrees into pv4[].z ----
__global__ void __launch_bounds__(NNZ_BLK) k_deg(const int* __restrict__ rows) {
    int t = blockIdx.x * NNZ_BLK + threadIdx.x;
    if (t >= NNZ_THREADS) return;
    const int4* r4 = (const int4*)(rows) + t * 2;
    int4 r0 = r4[0], r1 = r4[1];
    red1(&g_s.pv4[r0.x].z, 1.f); red1(&g_s.pv4[r0.y].z, 1.f);
    red1(&g_s.pv4[r0.z].z, 1.f); red1(&g_s.pv4[r0.w].z, 1.f);
    red1(&g_s.pv4[r1.x].z, 1.f); red1(&g_s.pv4[r1.y].z, 1.f);
    red1(&g_s.pv4[r1.z].z, 1.f); red1(&g_s.pv4[r1.w].z, 1.f);
}

// ---- phase 2: ze[e] += { (1/NV)/deg[v], 1 } ----
__global__ void __launch_bounds__(NNZ_BLK) k_scat1(const int* __restrict__ rows,
                                                   const int* __restrict__ cols) {
    int t = blockIdx.x * NNZ_BLK + threadIdx.x;
    if (t >= NNZ_THREADS) return;
    const int4* r4 = (const int4*)(rows) + t * 2;
    const int4* c4 = (const int4*)(cols) + t * 2;
    int4 r0 = r4[0], r1 = r4[1];
    int4 c0 = c4[0], c1 = c4[1];
    float d0 = __ldcg(&g_s.pv4[r0.x].z), d1 = __ldcg(&g_s.pv4[r0.y].z);
    float d2 = __ldcg(&g_s.pv4[r0.z].z), d3 = __ldcg(&g_s.pv4[r0.w].z);
    float d4 = __ldcg(&g_s.pv4[r1.x].z), d5 = __ldcg(&g_s.pv4[r1.y].z);
    float d6 = __ldcg(&g_s.pv4[r1.z].z), d7 = __ldcg(&g_s.pv4[r1.w].z);
    red2(&g_s.ze[c0.x], __fdividef(WP, d0), 1.f);
    red2(&g_s.ze[c0.y], __fdividef(WP, d1), 1.f);
    red2(&g_s.ze[c0.z], __fdividef(WP, d2), 1.f);
    red2(&g_s.ze[c0.w], __fdividef(WP, d3), 1.f);
    red2(&g_s.ze[c1.x], __fdividef(WP, d4), 1.f);
    red2(&g_s.ze[c1.y], __fdividef(WP, d5), 1.f);
    red2(&g_s.ze[c1.z], __fdividef(WP, d6), 1.f);
    red2(&g_s.ze[c1.w], __fdividef(WP, d7), 1.f);
}

// ---- phase 3: pv4[v].xy += { zp[e], edeg[e]/NE } ----
__global__ void __launch_bounds__(NNZ_BLK) k_gath1(const int* __restrict__ rows,
                                                   const int* __restrict__ cols) {
    int t = blockIdx.x * NNZ_BLK + threadIdx.x;
    if (t >= NNZ_THREADS) return;
    const int4* r4 = (const int4*)(rows) + t * 2;
    const int4* c4 = (const int4*)(cols) + t * 2;
    int4 r0 = r4[0], r1 = r4[1];
    int4 c0 = c4[0], c1 = c4[1];
    float2 z0 = __ldcg(&g_s.ze[c0.x]), z1 = __ldcg(&g_s.ze[c0.y]);
    float2 z2 = __ldcg(&g_s.ze[c0.z]), z3 = __ldcg(&g_s.ze[c0.w]);
    float2 z4 = __ldcg(&g_s.ze[c1.x]), z5 = __ldcg(&g_s.ze[c1.y]);
    float2 z6 = __ldcg(&g_s.ze[c1.z]), z7 = __ldcg(&g_s.ze[c1.w]);
    red2((float2*)&g_s.pv4[r0.x], z0.x, z0.y * WR);
    red2((float2*)&g_s.pv4[r0.y], z1.x, z1.y * WR);
    red2((float2*)&g_s.pv4[r0.z], z2.x, z2.y * WR);
    red2((float2*)&g_s.pv4[r0.w], z3.x, z3.y * WR);
    red2((float2*)&g_s.pv4[r1.x], z4.x, z4.y * WR);
    red2((float2*)&g_s.pv4[r1.y], z5.x, z5.y * WR);
    red2((float2*)&g_s.pv4[r1.z], z6.x, z6.y * WR);
    red2((float2*)&g_s.pv4[r1.w], z7.x, z7.y * WR);
}

// ---- phase 4: zp2[e] += (p_raw[v]+WP)/deg[v], q inline from one 16B gather ----
__global__ void __launch_bounds__(NNZ_BLK) k_scat2(const int* __restrict__ rows,
                                                   const int* __restrict__ cols) {
    int t = blockIdx.x * NNZ_BLK + threadIdx.x;
    if (t >= NNZ_THREADS) return;
    const int4* r4 = (const int4*)(rows) + t * 2;
    const int4* c4 = (const int4*)(cols) + t * 2;
    int4 r0 = r4[0], r1 = r4[1];
    int4 c0 = c4[0], c1 = c4[1];
    float4 v0 = __ldcg(&g_s.pv4[r0.x]), v1 = __ldcg(&g_s.pv4[r0.y]);
    float4 v2 = __ldcg(&g_s.pv4[r0.z]), v3 = __ldcg(&g_s.pv4[r0.w]);
    float4 v4 = __ldcg(&g_s.pv4[r1.x]), v5 = __ldcg(&g_s.pv4[r1.y]);
    float4 v6 = __ldcg(&g_s.pv4[r1.z]), v7 = __ldcg(&g_s.pv4[r1.w]);
    red1(&g_s.zp2[c0.x], __fdividef(v0.x + WP, v0.z));
    red1(&g_s.zp2[c0.y], __fdividef(v1.x + WP, v1.z));
    red1(&g_s.zp2[c0.z], __fdividef(v2.x + WP, v2.z));
    red1(&g_s.zp2[c0.w], __fdividef(v3.x + WP, v3.z));
    red1(&g_s.zp2[c1.x], __fdividef(v4.x + WP, v4.z));
    red1(&g_s.zp2[c1.y], __fdividef(v5.x + WP, v5.z));
    red1(&g_s.zp2[c1.z], __fdividef(v6.x + WP, v6.z));
    red1(&g_s.zp2[c1.w], __fdividef(v7.x + WP, v7.z));
}

// ---- phase 5: p2[v] += zp2[e] ----
__global__ void __launch_bounds__(NNZ_BLK) k_gath2(const int* __restrict__ rows,
                                                   const int* __restrict__ cols) {
    int t = blockIdx.x * NNZ_BLK + threadIdx.x;
    if (t >= NNZ_THREADS) return;
    const int4* r4 = (const int4*)(rows) + t * 2;
    const int4* c4 = (const int4*)(cols) + t * 2;
    int4 r0 = r4[0], r1 = r4[1];
    int4 c0 = c4[0], c1 = c4[1];
    float z0 = __ldcg(&g_s.zp2[c0.x]), z1 = __ldcg(&g_s.zp2[c0.y]);
    float z2 = __ldcg(&g_s.zp2[c0.z]), z3 = __ldcg(&g_s.zp2[c0.w]);
    float z4 = __ldcg(&g_s.zp2[c1.x]), z5 = __ldcg(&g_s.zp2[c1.y]);
    float z6 = __ldcg(&g_s.zp2[c1.z]), z7 = __ldcg(&g_s.zp2[c1.w]);
    red1(&g_s.p2[r0.x], z0); red1(&g_s.p2[r0.y], z1);
    red1(&g_s.p2[r0.z], z2); red1(&g_s.p2[r0.w], z3);
    red1(&g_s.p2[r1.x], z4); red1(&g_s.p2[r1.y], z5);
    red1(&g_s.p2[r1.z], z6); red1(&g_s.p2[r1.w], z7);
}

// ---- phase 6: per-vertex reduction (2 vertices/thread, float4 x0 reads)
//      + fused final GEMV (ticket pattern) ----
__global__ void __launch_bounds__(RED_BLK)
k_reduce_final(const float* __restrict__ x0,
               const float* __restrict__ W0, const float* __restrict__ b0,
               const float* __restrict__ Wl0, const float* __restrict__ bl0,
               const float* __restrict__ Wl1, const float* __restrict__ bl1,
               const float* __restrict__ Wo0, const float* __restrict__ bo0,
               const float* __restrict__ Wo1, const float* __restrict__ bo1,
               float* __restrict__ out) {
    int t = blockIdx.x * RED_BLK + threadIdx.x;
    float vals[31];
#pragma unroll
    for (int k = 0; k < 31; k++) vals[k] = 0.f;

    if (t < NV / 2) {
        int v0 = 2 * t;
        float4 pa = g_s.pv4[v0];
        float4 pb = g_s.pv4[v0 + 1];
        float2 p2pair = *(const float2*)&g_s.p2[v0];
        float pvA  = pa.x + WP;
        float p2A  = p2pair.x + pvA;
        float r2A  = pa.y + pa.z * WR;
        float pvB  = pb.x + WP;
        float p2B  = p2pair.y + pvB;
        float r2B  = pb.y + pb.z * WR;

        // 2 rows of 14 floats = 112 bytes = 7 aligned float4 loads
        const float4* xr = (const float4*)(x0 + (long long)v0 * DIN);
        float xs[28];
#pragma unroll
        for (int q = 0; q < 7; q++) {
            float4 f = xr[q];
            xs[q * 4 + 0] = f.x; xs[q * 4 + 1] = f.y;
            xs[q * 4 + 2] = f.z; xs[q * 4 + 3] = f.w;
        }
#pragma unroll
        for (int j = 0; j < DIN; j++) {
            vals[j]      = p2A * xs[j] + p2B * xs[14 + j];
            vals[14 + j] = r2A * xs[j] + r2B * xs[14 + j];
        }
        vals[28] = pvA + pvB;
        vals[29] = p2A + p2B;
        vals[30] = r2A + r2B;
    }
#pragma unroll
    for (int k = 0; k < 31; k++) {
#pragma unroll
        for (int off = 16; off > 0; off >>= 1)
            vals[k] += __shfl_down_sync(0xffffffffu, vals[k], off);
    }
    __shared__ float sh[8 * 31];
    int warp = threadIdx.x >> 5, lane = threadIdx.x & 31;
    if (lane == 0) {
#pragma unroll
        for (int k = 0; k < 31; k++) sh[warp * 31 + k] = vals[k];
    }
    __syncthreads();
    if (threadIdx.x < 31) {
        float s = 0.f;
#pragma unroll
        for (int w = 0; w < 8; w++) s += sh[w * 31 + threadIdx.x];
        atomicAdd(&g_s.acc[threadIdx.x], s);
    }

    // ---- ticket: last block runs the tiny GEMV chain ----
    __threadfence();
    __shared__ unsigned int is_last;
    if (threadIdx.x == 0)
        is_last = (atomicInc(&g_s.tick, gridDim.x - 1) == gridDim.x - 1) ? 1u : 0u;
    __syncthreads();
    if (!is_last) return;
    __threadfence();

    __shared__ float a0[HID], c0[HID], a1[HID], c1[HID], red[HID];
    int h = threadIdx.x;
    float sp  = g_s.acc[28];
    float sp2 = g_s.acc[29];
    float sr2 = g_s.acc[30];
    float sr  = (float)NNZt / (float)NE;   // 1^T (deg/NE) exactly

    if (h < HID) {
        float sa = 0.f, sc = 0.f;
#pragma unroll
        for (int j = 0; j < DIN; j++) {
            float w = W0[j * HID + h];
            sa += g_s.acc[j] * w;
            sc += g_s.acc[14 + j] * w;
        }
        a0[h] = sa + sp2 * b0[h];
        c0[h] = sc + sr2 * b0[h];
    }
    __syncthreads();
    if (h < HID) {
        float sa = 0.f, sc = 0.f;
        for (int m = 0; m < HID; m++) {
            float w = Wl0[m * HID + h];
            sa += a0[m] * w;
            sc += c0[m] * w;
        }
        a1[h] = sa + sp2 * bl0[h];
        c1[h] = sc + sr2 * bl0[h];
    }
    __syncthreads();
    if (h < HID) {
        float sa = 0.f, sc = 0.f;
        for (int m = 0; m < HID; m++) {
            float w = Wl1[m * HID + h];
            sa += a1[m] * w;
            sc += c1[m] * w;
        }
        float a2h = sa + sp * bl1[h];   // p^T h2
        float c2h = sc + sr * bl1[h];   // r^T h2
        red[h] = a2h * Wo0[h] + c2h * Wo1[h];
    }
    __syncthreads();
    for (int s = HID / 2; s > 0; s >>= 1) {
        if (h < s) red[h] += red[h + s];
        __syncthreads();
    }
    if (h == 0) out[0] = red[0] + bo0[0] + bo1[0];
}

extern "C" void kernel_launch(void* const* d_in, const int* in_sizes, int n_in,
                              void* d_out, int out_size) {
    const float* x_0  = (const float*)d_in[0];
    const int*   rows = (const int*)d_in[2];
    const int*   cols = (const int*)d_in[3];
    const float* W0   = (const float*)d_in[4];
    const float* b0   = (const float*)d_in[5];
    const float* Wl0  = (const float*)d_in[8];
    const float* bl0  = (const float*)d_in[9];
    const float* Wl1  = (const float*)d_in[10];
    const float* bl1  = (const float*)d_in[11];
    const float* Wo0  = (const float*)d_in[12];
    const float* bo0  = (const float*)d_in[13];
    const float* Wo1  = (const float*)d_in[14];
    const float* bo1  = (const float*)d_in[15];
    float* out = (float*)d_out;

    void* p_s;
    cudaGetSymbolAddress(&p_s, g_s);
    cudaMemsetAsync(p_s, 0, sizeof(Scratch));

    k_deg  <<<NNZ_GRID, NNZ_BLK>>>(rows);
    k_scat1<<<NNZ_GRID, NNZ_BLK>>>(rows, cols);
    k_gath1<<<NNZ_GRID, NNZ_BLK>>>(rows, cols);
    k_scat2<<<NNZ_GRID, NNZ_BLK>>>(rows, cols);
    k_gath2<<<NNZ_GRID, NNZ_BLK>>>(rows, cols);
    k_reduce_final<<<RED_GRID, RED_BLK>>>(x_0, W0, b0, Wl0, bl0, Wl1, bl1,
                                          Wo0, bo0, Wo1, bo1, out);
}